// round 6
// baseline (speedup 1.0000x reference)
#include <cuda_runtime.h>

#define N_   4
#define C_   64
#define V_   25
#define T_   300
#define M_   2
#define H_   8
#define HD_  32
#define E_   256
#define B_   8          // N_*M_
#define NTOK 60000      // B_*V_*T_
#define QKVW 768

typedef unsigned long long u64;

// ---- packed f32x2 helpers (Blackwell FFMA2 path) --------------------------
__device__ __forceinline__ void ffma2(u64& d, u64 a, u64 b) {
    asm("fma.rn.f32x2 %0, %1, %2, %0;" : "+l"(d) : "l"(a), "l"(b));
}
__device__ __forceinline__ u64 fmul2(u64 a, u64 b) {
    u64 r; asm("mul.rn.f32x2 %0, %1, %2;" : "=l"(r) : "l"(a), "l"(b)); return r;
}
__device__ __forceinline__ u64 fadd2(u64 a, u64 b) {
    u64 r; asm("add.rn.f32x2 %0, %1, %2;" : "=l"(r) : "l"(a), "l"(b)); return r;
}
__device__ __forceinline__ u64 pack2(float lo, float hi) {
    u64 r; asm("mov.b64 %0, {%1, %2};" : "=l"(r) : "f"(lo), "f"(hi)); return r;
}
__device__ __forceinline__ float2 unpack2(u64 a) {
    float lo, hi; asm("mov.b64 {%0, %1}, %2;" : "=f"(lo), "=f"(hi) : "l"(a));
    return make_float2(lo, hi);
}

// Scratch (allocation-free: device globals)
__device__ float g_xp[NTOK * C_];                 // packed tokens [60000][64]
__device__ float g_qkv[(size_t)NTOK * QKVW];      // [60000][768] = q|k|v
__device__ float g_ao[(size_t)NTOK * E_];         // attention out [60000][256]

// ---------------------------------------------------------------------------
// Kernel 1: pack x (N,C,V,T,M) -> xp [tok][C] with tok = ((n*2+m)*25+v)*300+t
// ---------------------------------------------------------------------------
__global__ void pack_kernel(const float* __restrict__ x) {
    int i = blockIdx.x * 256 + threadIdx.x;   // exactly 3,840,000 threads
    int m = i & 1;
    int t = (i >> 1) % 300;
    int r = i / 600;
    int v = r % 25; r /= 25;
    int c = r & 63;
    int n = r >> 6;
    int tok = (((n * 2 + m) * 25 + v) * 300 + t);
    g_xp[tok * 64 + c] = x[i];
}

// ---------------------------------------------------------------------------
// Kernel 2: QKV GEMM  [60000x64] @ [64x768] + b  -> g_qkv  (FFMA2 mainloop)
// ---------------------------------------------------------------------------
__global__ __launch_bounds__(256) void qkv_gemm(const float* __restrict__ w,
                                                const float* __restrict__ bias) {
    __shared__ __align__(16) float As[64][65];
    __shared__ __align__(16) float Bs[64][64];
    int m0 = blockIdx.x * 64;
    int n0 = blockIdx.y * 64;
    int tid = threadIdx.x;
    int tx = tid & 15, ty = tid >> 4;

#pragma unroll
    for (int it = 0; it < 4; ++it) {
        int lin = tid + it * 256;           // float4 index, 0..1023
        int row = lin >> 4;
        int c4  = (lin & 15) * 4;
        float4 f = make_float4(0.f, 0.f, 0.f, 0.f);
        if (m0 + row < NTOK)
            f = *(const float4*)(g_xp + (size_t)(m0 + row) * 64 + c4);
        As[row][c4 + 0] = f.x; As[row][c4 + 1] = f.y;
        As[row][c4 + 2] = f.z; As[row][c4 + 3] = f.w;
        *(float4*)&Bs[row][c4] = *(const float4*)(w + row * QKVW + n0 + c4);
    }
    __syncthreads();

    float4 bb = *(const float4*)(bias + n0 + tx * 4);
    u64 acc[4][2];
#pragma unroll
    for (int i = 0; i < 4; ++i) {
        acc[i][0] = pack2(bb.x, bb.y);
        acc[i][1] = pack2(bb.z, bb.w);
    }
#pragma unroll
    for (int c = 0; c < 64; ++c) {
        u64 p0 = pack2(As[ty * 4 + 0][c], As[ty * 4 + 0][c]);
        u64 p1 = pack2(As[ty * 4 + 1][c], As[ty * 4 + 1][c]);
        u64 p2 = pack2(As[ty * 4 + 2][c], As[ty * 4 + 2][c]);
        u64 p3 = pack2(As[ty * 4 + 3][c], As[ty * 4 + 3][c]);
        ulonglong2 b2 = *(const ulonglong2*)&Bs[c][tx * 4];
        ffma2(acc[0][0], p0, b2.x); ffma2(acc[0][1], p0, b2.y);
        ffma2(acc[1][0], p1, b2.x); ffma2(acc[1][1], p1, b2.y);
        ffma2(acc[2][0], p2, b2.x); ffma2(acc[2][1], p2, b2.y);
        ffma2(acc[3][0], p3, b2.x); ffma2(acc[3][1], p3, b2.y);
    }
#pragma unroll
    for (int i = 0; i < 4; ++i) {
        int row = m0 + ty * 4 + i;
        if (row < NTOK) {
            float2 lo = unpack2(acc[i][0]);
            float2 hi = unpack2(acc[i][1]);
            float4 f = make_float4(lo.x, lo.y, hi.x, hi.y);
            *(float4*)(g_qkv + (size_t)row * QKVW + n0 + tx * 4) = f;
        }
    }
}

// ---------------------------------------------------------------------------
// Kernel 3: attention. 2 q-blocks of 150 queries (160 threads). FFMA2 inner.
// ---------------------------------------------------------------------------
#define QBLK 150
#define NTHR 160
#define BIAS_ROWS 449
#define BIAS_PITCH 36
#define KC 60
#define ATTN_SMEM ((BIAS_ROWS * BIAS_PITCH + 2 * KC * 32) * 4)

__global__ __launch_bounds__(NTHR, 2) void attn_kernel(const float* __restrict__ bias_table) {
    extern __shared__ float sm[];
    float* bias_s = sm;                          // 449 * 36
    float* ks = sm + BIAS_ROWS * BIAS_PITCH;     // 60 * 32 (pre-scaled)
    float* vs = ks + KC * 32;                    // 60 * 32

    int g  = blockIdx.x;          // 0..1599
    int bv = g >> 3;
    int h  = g & 7;
    int q0 = blockIdx.y * QBLK;   // 0 or 150
    int tid = threadIdx.x;
    const float* qkv_bv = g_qkv + (size_t)bv * (T_ * QKVW);

    // stage bias rows [q0, q0+448] (always 449 valid rows, 599 total in table)
    for (int i4 = tid; i4 < BIAS_ROWS * 8; i4 += NTHR) {
        int r = i4 >> 3, d4 = (i4 & 7) * 4;
        *(float4*)(bias_s + r * BIAS_PITCH + d4) =
            *(const float4*)(bias_table + (q0 + r) * 32 + d4);
    }

    int l = q0 + tid;
    bool active = (tid < QBLK) && (l < T_);
    u64 q2[16];
    if (active) {
        const ulonglong2* qp = (const ulonglong2*)(qkv_bv + (size_t)l * QKVW + h * 32);
#pragma unroll
        for (int i = 0; i < 8; ++i) {
            ulonglong2 f = qp[i];
            q2[2 * i] = f.x; q2[2 * i + 1] = f.y;
        }
    }
    u64 o2[16];
#pragma unroll
    for (int d = 0; d < 16; ++d) o2[d] = 0ull;
    float mx = -3.0e38f, ssum = 0.f;

    for (int r0 = 0; r0 < T_; r0 += KC) {
        __syncthreads();
        for (int i4 = tid; i4 < KC * 8; i4 += NTHR) {
            int r = i4 >> 3, d4 = (i4 & 7) * 4;
            const float* kp = qkv_bv + (size_t)(r0 + r) * QKVW + 256 + h * 32 + d4;
            float4 kf = *(const float4*)kp;
            kf.x *= 0.0625f; kf.y *= 0.0625f; kf.z *= 0.0625f; kf.w *= 0.0625f;   // E^-0.5
            *(float4*)(ks + r * 32 + d4) = kf;
            *(float4*)(vs + r * 32 + d4) = *(const float4*)(kp + 256);
        }
        __syncthreads();
        if (active) {
#pragma unroll 1
            for (int rr = 0; rr < KC; rr += 10) {
                float s[10];
                int brow0 = tid - (r0 + rr) + 299;    // local bias row, in [0, 448]
#pragma unroll
                for (int j = 0; j < 10; ++j) {
                    const ulonglong2* k2 = (const ulonglong2*)(ks + (rr + j) * 32);
                    const ulonglong2* b2 = (const ulonglong2*)(bias_s + (brow0 - j) * BIAS_PITCH);
                    u64 a0 = 0ull, a1 = 0ull, a2 = 0ull, a3 = 0ull;
#pragma unroll
                    for (int i = 0; i < 8; ++i) {
                        ulonglong2 kf = k2[i];
                        ulonglong2 bf = b2[i];
                        ffma2(a0, q2[2 * i],     kf.x);
                        ffma2(a1, q2[2 * i + 1], kf.y);
                        ffma2(a2, q2[2 * i],     bf.x);
                        ffma2(a3, q2[2 * i + 1], bf.y);
                    }
                    u64 u = fadd2(fadd2(a0, a1), fadd2(a2, a3));
                    float2 f = unpack2(u);
                    s[j] = f.x + f.y;
                }
                float nm = mx;
#pragma unroll
                for (int j = 0; j < 10; ++j) nm = fmaxf(nm, s[j]);
                float corr = __expf(mx - nm);
                mx = nm;
                ssum *= corr;
                u64 cc = pack2(corr, corr);
#pragma unroll
                for (int d = 0; d < 16; ++d) o2[d] = fmul2(o2[d], cc);
#pragma unroll
                for (int j = 0; j < 10; ++j) {
                    float p = __expf(s[j] - nm);
                    ssum += p;
                    u64 pp = pack2(p, p);
                    const ulonglong2* v2p = (const ulonglong2*)(vs + (rr + j) * 32);
#pragma unroll
                    for (int i = 0; i < 8; ++i) {
                        ulonglong2 vf = v2p[i];
                        ffma2(o2[2 * i],     pp, vf.x);
                        ffma2(o2[2 * i + 1], pp, vf.y);
                    }
                }
            }
        }
    }

    if (active) {
        float inv = 1.0f / ssum;
        float* op = g_ao + ((size_t)bv * T_ + l) * E_ + h * 32;
#pragma unroll
        for (int i = 0; i < 8; ++i) {
            float2 lo = unpack2(o2[2 * i]);
            float2 hi = unpack2(o2[2 * i + 1]);
            float4 f = make_float4(lo.x * inv, lo.y * inv, hi.x * inv, hi.y * inv);
            *(float4*)(op + i * 4) = f;
        }
    }
}

// ---------------------------------------------------------------------------
// Kernel 4: merge GEMM [60000x256]@[256x64] + b, scatter (FFMA2 mainloop)
// ---------------------------------------------------------------------------
__global__ __launch_bounds__(256) void merge_gemm(const float* __restrict__ w,
                                                  const float* __restrict__ bias,
                                                  float* __restrict__ out) {
    __shared__ __align__(16) float As[64][65];
    __shared__ __align__(16) float Bs[64][64];
    int m0 = blockIdx.x * 64;
    int tid = threadIdx.x;
    int tx = tid & 15, ty = tid >> 4;

    float4 bb = *(const float4*)(bias + tx * 4);
    u64 acc[4][2];
#pragma unroll
    for (int i = 0; i < 4; ++i) {
        acc[i][0] = pack2(bb.x, bb.y);
        acc[i][1] = pack2(bb.z, bb.w);
    }

    for (int k0 = 0; k0 < 256; k0 += 64) {
        __syncthreads();
#pragma unroll
        for (int it = 0; it < 4; ++it) {
            int lin = tid + it * 256;
            int row = lin >> 4;
            int c4  = (lin & 15) * 4;
            float4 f = make_float4(0.f, 0.f, 0.f, 0.f);
            if (m0 + row < NTOK)
                f = *(const float4*)(g_ao + (size_t)(m0 + row) * E_ + k0 + c4);
            As[row][c4 + 0] = f.x; As[row][c4 + 1] = f.y;
            As[row][c4 + 2] = f.z; As[row][c4 + 3] = f.w;
            *(float4*)&Bs[row][c4] = *(const float4*)(w + (k0 + row) * 64 + c4);
        }
        __syncthreads();
#pragma unroll
        for (int c = 0; c < 64; ++c) {
            u64 p0 = pack2(As[ty * 4 + 0][c], As[ty * 4 + 0][c]);
            u64 p1 = pack2(As[ty * 4 + 1][c], As[ty * 4 + 1][c]);
            u64 p2 = pack2(As[ty * 4 + 2][c], As[ty * 4 + 2][c]);
            u64 p3 = pack2(As[ty * 4 + 3][c], As[ty * 4 + 3][c]);
            ulonglong2 b2 = *(const ulonglong2*)&Bs[c][tx * 4];
            ffma2(acc[0][0], p0, b2.x); ffma2(acc[0][1], p0, b2.y);
            ffma2(acc[1][0], p1, b2.x); ffma2(acc[1][1], p1, b2.y);
            ffma2(acc[2][0], p2, b2.x); ffma2(acc[2][1], p2, b2.y);
            ffma2(acc[3][0], p3, b2.x); ffma2(acc[3][1], p3, b2.y);
        }
    }

#pragma unroll
    for (int i = 0; i < 4; ++i) {
        int tok = m0 + ty * 4 + i;
        if (tok < NTOK) {
            int t  = tok % 300;
            int bvv = tok / 300;
            int v  = bvv % 25;
            int b  = bvv / 25;
            int n  = b >> 1;
            int mm = b & 1;
            size_t base = (size_t)n * 960000 + (size_t)v * 600 + t * 2 + mm;
            float2 lo = unpack2(acc[i][0]);
            float2 hi = unpack2(acc[i][1]);
            float r[4] = {lo.x, lo.y, hi.x, hi.y};
#pragma unroll
            for (int j = 0; j < 4; ++j)
                out[base + (size_t)(tx * 4 + j) * 15000] = r[j];
        }
    }
}

// ---------------------------------------------------------------------------
extern "C" void kernel_launch(void* const* d_in, const int* in_sizes, int n_in,
                              void* d_out, int out_size) {
    const float* x          = (const float*)d_in[0];
    const float* w_qkv      = (const float*)d_in[1];
    const float* b_qkv      = (const float*)d_in[2];
    const float* w_merge    = (const float*)d_in[3];
    const float* b_merge    = (const float*)d_in[4];
    const float* bias_table = (const float*)d_in[5];
    float* out = (float*)d_out;

    cudaFuncSetAttribute(attn_kernel, cudaFuncAttributeMaxDynamicSharedMemorySize,
                         ATTN_SMEM);

    pack_kernel<<<15000, 256>>>(x);

    dim3 g1((NTOK + 63) / 64, QKVW / 64);
    qkv_gemm<<<g1, 256>>>(w_qkv, b_qkv);

    dim3 g2(B_ * V_ * H_, 2);   // 1600 groups x 2 query blocks of 150
    attn_kernel<<<g2, NTHR, ATTN_SMEM>>>(bias_table);

    merge_gemm<<<(NTOK + 63) / 64, 256>>>(w_merge, b_merge, out);
}

// round 9
// speedup vs baseline: 1.0011x; 1.0011x over previous
#include <cuda_runtime.h>

#define N_   4
#define C_   64
#define V_   25
#define T_   300
#define M_   2
#define H_   8
#define HD_  32
#define E_   256
#define B_   8          // N_*M_
#define NTOK 60000      // B_*V_*T_
#define QKVW 768

typedef unsigned long long u64;

// ---- packed f32x2 helpers (Blackwell FFMA2 path) --------------------------
__device__ __forceinline__ void ffma2(u64& d, u64 a, u64 b) {
    asm("fma.rn.f32x2 %0, %1, %2, %0;" : "+l"(d) : "l"(a), "l"(b));
}
__device__ __forceinline__ u64 fmul2(u64 a, u64 b) {
    u64 r; asm("mul.rn.f32x2 %0, %1, %2;" : "=l"(r) : "l"(a), "l"(b)); return r;
}
__device__ __forceinline__ u64 fadd2(u64 a, u64 b) {
    u64 r; asm("add.rn.f32x2 %0, %1, %2;" : "=l"(r) : "l"(a), "l"(b)); return r;
}
__device__ __forceinline__ u64 pack2(float lo, float hi) {
    u64 r; asm("mov.b64 %0, {%1, %2};" : "=l"(r) : "f"(lo), "f"(hi)); return r;
}
__device__ __forceinline__ float2 unpack2(u64 a) {
    float lo, hi; asm("mov.b64 {%0, %1}, %2;" : "=f"(lo), "=f"(hi) : "l"(a));
    return make_float2(lo, hi);
}

// Scratch (allocation-free: device globals)
__device__ float g_xp[NTOK * C_];                 // packed tokens [60000][64]
__device__ float g_qkv[(size_t)NTOK * QKVW];      // [60000][768] = q|k|v
__device__ float g_ao[(size_t)NTOK * E_];         // attention out [60000][256]

// ---------------------------------------------------------------------------
// Kernel 1: pack x (N,C,V,T,M) -> xp [tok][C] with tok = ((n*2+m)*25+v)*300+t
// ---------------------------------------------------------------------------
__global__ void pack_kernel(const float* __restrict__ x) {
    int i = blockIdx.x * 256 + threadIdx.x;   // exactly 3,840,000 threads
    int m = i & 1;
    int t = (i >> 1) % 300;
    int r = i / 600;
    int v = r % 25; r /= 25;
    int c = r & 63;
    int n = r >> 6;
    int tok = (((n * 2 + m) * 25 + v) * 300 + t);
    g_xp[tok * 64 + c] = x[i];
}

// ---------------------------------------------------------------------------
// Kernel 2: QKV GEMM  [60000x64] @ [64x768] + b  -> g_qkv  (FFMA2 mainloop)
// ---------------------------------------------------------------------------
__global__ __launch_bounds__(256) void qkv_gemm(const float* __restrict__ w,
                                                const float* __restrict__ bias) {
    __shared__ __align__(16) float As[64][65];
    __shared__ __align__(16) float Bs[64][64];
    int m0 = blockIdx.x * 64;
    int n0 = blockIdx.y * 64;
    int tid = threadIdx.x;
    int tx = tid & 15, ty = tid >> 4;

#pragma unroll
    for (int it = 0; it < 4; ++it) {
        int lin = tid + it * 256;           // float4 index, 0..1023
        int row = lin >> 4;
        int c4  = (lin & 15) * 4;
        float4 f = make_float4(0.f, 0.f, 0.f, 0.f);
        if (m0 + row < NTOK)
            f = *(const float4*)(g_xp + (size_t)(m0 + row) * 64 + c4);
        As[row][c4 + 0] = f.x; As[row][c4 + 1] = f.y;
        As[row][c4 + 2] = f.z; As[row][c4 + 3] = f.w;
        *(float4*)&Bs[row][c4] = *(const float4*)(w + row * QKVW + n0 + c4);
    }
    __syncthreads();

    float4 bb = *(const float4*)(bias + n0 + tx * 4);
    u64 acc[4][2];
#pragma unroll
    for (int i = 0; i < 4; ++i) {
        acc[i][0] = pack2(bb.x, bb.y);
        acc[i][1] = pack2(bb.z, bb.w);
    }
#pragma unroll
    for (int c = 0; c < 64; ++c) {
        u64 p0 = pack2(As[ty * 4 + 0][c], As[ty * 4 + 0][c]);
        u64 p1 = pack2(As[ty * 4 + 1][c], As[ty * 4 + 1][c]);
        u64 p2 = pack2(As[ty * 4 + 2][c], As[ty * 4 + 2][c]);
        u64 p3 = pack2(As[ty * 4 + 3][c], As[ty * 4 + 3][c]);
        ulonglong2 b2 = *(const ulonglong2*)&Bs[c][tx * 4];
        ffma2(acc[0][0], p0, b2.x); ffma2(acc[0][1], p0, b2.y);
        ffma2(acc[1][0], p1, b2.x); ffma2(acc[1][1], p1, b2.y);
        ffma2(acc[2][0], p2, b2.x); ffma2(acc[2][1], p2, b2.y);
        ffma2(acc[3][0], p3, b2.x); ffma2(acc[3][1], p3, b2.y);
    }
#pragma unroll
    for (int i = 0; i < 4; ++i) {
        int row = m0 + ty * 4 + i;
        if (row < NTOK) {
            float2 lo = unpack2(acc[i][0]);
            float2 hi = unpack2(acc[i][1]);
            float4 f = make_float4(lo.x, lo.y, hi.x, hi.y);
            *(float4*)(g_qkv + (size_t)row * QKVW + n0 + tx * 4) = f;
        }
    }
}

// ---------------------------------------------------------------------------
// Kernel 3: attention. 2 q-blocks of 150 queries (160 threads). FFMA2 inner.
// ---------------------------------------------------------------------------
#define QBLK 150
#define NTHR 160
#define BIAS_ROWS 449
#define BIAS_PITCH 36
#define KC 60
#define ATTN_SMEM ((BIAS_ROWS * BIAS_PITCH + 2 * KC * 32) * 4)

__global__ __launch_bounds__(NTHR, 2) void attn_kernel(const float* __restrict__ bias_table) {
    extern __shared__ float sm[];
    float* bias_s = sm;                          // 449 * 36
    float* ks = sm + BIAS_ROWS * BIAS_PITCH;     // 60 * 32 (pre-scaled)
    float* vs = ks + KC * 32;                    // 60 * 32

    int g  = blockIdx.x;          // 0..1599
    int bv = g >> 3;
    int h  = g & 7;
    int q0 = blockIdx.y * QBLK;   // 0 or 150
    int tid = threadIdx.x;
    const float* qkv_bv = g_qkv + (size_t)bv * (T_ * QKVW);

    // stage bias rows [q0, q0+448] (always 449 valid rows, 599 total in table)
    for (int i4 = tid; i4 < BIAS_ROWS * 8; i4 += NTHR) {
        int r = i4 >> 3, d4 = (i4 & 7) * 4;
        *(float4*)(bias_s + r * BIAS_PITCH + d4) =
            *(const float4*)(bias_table + (q0 + r) * 32 + d4);
    }

    int l = q0 + tid;
    bool active = (tid < QBLK) && (l < T_);
    u64 q2[16];
    if (active) {
        const ulonglong2* qp = (const ulonglong2*)(qkv_bv + (size_t)l * QKVW + h * 32);
#pragma unroll
        for (int i = 0; i < 8; ++i) {
            ulonglong2 f = qp[i];
            q2[2 * i] = f.x; q2[2 * i + 1] = f.y;
        }
    }
    u64 o2[16];
#pragma unroll
    for (int d = 0; d < 16; ++d) o2[d] = 0ull;
    float mx = -3.0e38f, ssum = 0.f;

    for (int r0 = 0; r0 < T_; r0 += KC) {
        __syncthreads();
        for (int i4 = tid; i4 < KC * 8; i4 += NTHR) {
            int r = i4 >> 3, d4 = (i4 & 7) * 4;
            const float* kp = qkv_bv + (size_t)(r0 + r) * QKVW + 256 + h * 32 + d4;
            float4 kf = *(const float4*)kp;
            kf.x *= 0.0625f; kf.y *= 0.0625f; kf.z *= 0.0625f; kf.w *= 0.0625f;   // E^-0.5
            *(float4*)(ks + r * 32 + d4) = kf;
            *(float4*)(vs + r * 32 + d4) = *(const float4*)(kp + 256);
        }
        __syncthreads();
        if (active) {
#pragma unroll 1
            for (int rr = 0; rr < KC; rr += 10) {
                float s[10];
                int brow0 = tid - (r0 + rr) + 299;    // local bias row, in [0, 448]
#pragma unroll
                for (int j = 0; j < 10; ++j) {
                    const ulonglong2* k2 = (const ulonglong2*)(ks + (rr + j) * 32);
                    const ulonglong2* b2 = (const ulonglong2*)(bias_s + (brow0 - j) * BIAS_PITCH);
                    u64 a0 = 0ull, a1 = 0ull, a2 = 0ull, a3 = 0ull;
#pragma unroll
                    for (int i = 0; i < 8; ++i) {
                        ulonglong2 kf = k2[i];
                        ulonglong2 bf = b2[i];
                        ffma2(a0, q2[2 * i],     kf.x);
                        ffma2(a1, q2[2 * i + 1], kf.y);
                        ffma2(a2, q2[2 * i],     bf.x);
                        ffma2(a3, q2[2 * i + 1], bf.y);
                    }
                    u64 u = fadd2(fadd2(a0, a1), fadd2(a2, a3));
                    float2 f = unpack2(u);
                    s[j] = f.x + f.y;
                }
                float nm = mx;
#pragma unroll
                for (int j = 0; j < 10; ++j) nm = fmaxf(nm, s[j]);
                float corr = __expf(mx - nm);
                mx = nm;
                ssum *= corr;
                u64 cc = pack2(corr, corr);
#pragma unroll
                for (int d = 0; d < 16; ++d) o2[d] = fmul2(o2[d], cc);
#pragma unroll
                for (int j = 0; j < 10; ++j) {
                    float p = __expf(s[j] - nm);
                    ssum += p;
                    u64 pp = pack2(p, p);
                    const ulonglong2* v2p = (const ulonglong2*)(vs + (rr + j) * 32);
#pragma unroll
                    for (int i = 0; i < 8; ++i) {
                        ulonglong2 vf = v2p[i];
                        ffma2(o2[2 * i],     pp, vf.x);
                        ffma2(o2[2 * i + 1], pp, vf.y);
                    }
                }
            }
        }
    }

    if (active) {
        float inv = 1.0f / ssum;
        float* op = g_ao + ((size_t)bv * T_ + l) * E_ + h * 32;
#pragma unroll
        for (int i = 0; i < 8; ++i) {
            float2 lo = unpack2(o2[2 * i]);
            float2 hi = unpack2(o2[2 * i + 1]);
            float4 f = make_float4(lo.x * inv, lo.y * inv, hi.x * inv, hi.y * inv);
            *(float4*)(op + i * 4) = f;
        }
    }
}

// ---------------------------------------------------------------------------
// Kernel 4: merge GEMM [60000x256]@[256x64] + b, scatter (FFMA2 mainloop)
// ---------------------------------------------------------------------------
__global__ __launch_bounds__(256) void merge_gemm(const float* __restrict__ w,
                                                  const float* __restrict__ bias,
                                                  float* __restrict__ out) {
    __shared__ __align__(16) float As[64][65];
    __shared__ __align__(16) float Bs[64][64];
    int m0 = blockIdx.x * 64;
    int tid = threadIdx.x;
    int tx = tid & 15, ty = tid >> 4;

    float4 bb = *(const float4*)(bias + tx * 4);
    u64 acc[4][2];
#pragma unroll
    for (int i = 0; i < 4; ++i) {
        acc[i][0] = pack2(bb.x, bb.y);
        acc[i][1] = pack2(bb.z, bb.w);
    }

    for (int k0 = 0; k0 < 256; k0 += 64) {
        __syncthreads();
#pragma unroll
        for (int it = 0; it < 4; ++it) {
            int lin = tid + it * 256;
            int row = lin >> 4;
            int c4  = (lin & 15) * 4;
            float4 f = make_float4(0.f, 0.f, 0.f, 0.f);
            if (m0 + row < NTOK)
                f = *(const float4*)(g_ao + (size_t)(m0 + row) * E_ + k0 + c4);
            As[row][c4 + 0] = f.x; As[row][c4 + 1] = f.y;
            As[row][c4 + 2] = f.z; As[row][c4 + 3] = f.w;
            *(float4*)&Bs[row][c4] = *(const float4*)(w + (k0 + row) * 64 + c4);
        }
        __syncthreads();
#pragma unroll
        for (int c = 0; c < 64; ++c) {
            u64 p0 = pack2(As[ty * 4 + 0][c], As[ty * 4 + 0][c]);
            u64 p1 = pack2(As[ty * 4 + 1][c], As[ty * 4 + 1][c]);
            u64 p2 = pack2(As[ty * 4 + 2][c], As[ty * 4 + 2][c]);
            u64 p3 = pack2(As[ty * 4 + 3][c], As[ty * 4 + 3][c]);
            ulonglong2 b2 = *(const ulonglong2*)&Bs[c][tx * 4];
            ffma2(acc[0][0], p0, b2.x); ffma2(acc[0][1], p0, b2.y);
            ffma2(acc[1][0], p1, b2.x); ffma2(acc[1][1], p1, b2.y);
            ffma2(acc[2][0], p2, b2.x); ffma2(acc[2][1], p2, b2.y);
            ffma2(acc[3][0], p3, b2.x); ffma2(acc[3][1], p3, b2.y);
        }
    }

#pragma unroll
    for (int i = 0; i < 4; ++i) {
        int tok = m0 + ty * 4 + i;
        if (tok < NTOK) {
            int t  = tok % 300;
            int bvv = tok / 300;
            int v  = bvv % 25;
            int b  = bvv / 25;
            int n  = b >> 1;
            int mm = b & 1;
            size_t base = (size_t)n * 960000 + (size_t)v * 600 + t * 2 + mm;
            float2 lo = unpack2(acc[i][0]);
            float2 hi = unpack2(acc[i][1]);
            float r[4] = {lo.x, lo.y, hi.x, hi.y};
#pragma unroll
            for (int j = 0; j < 4; ++j)
                out[base + (size_t)(tx * 4 + j) * 15000] = r[j];
        }
    }
}

// ---------------------------------------------------------------------------
extern "C" void kernel_launch(void* const* d_in, const int* in_sizes, int n_in,
                              void* d_out, int out_size) {
    const float* x          = (const float*)d_in[0];
    const float* w_qkv      = (const float*)d_in[1];
    const float* b_qkv      = (const float*)d_in[2];
    const float* w_merge    = (const float*)d_in[3];
    const float* b_merge    = (const float*)d_in[4];
    const float* bias_table = (const float*)d_in[5];
    float* out = (float*)d_out;

    cudaFuncSetAttribute(attn_kernel, cudaFuncAttributeMaxDynamicSharedMemorySize,
                         ATTN_SMEM);

    pack_kernel<<<15000, 256>>>(x);

    dim3 g1((NTOK + 63) / 64, QKVW / 64);
    qkv_gemm<<<g1, 256>>>(w_qkv, b_qkv);

    dim3 g2(B_ * V_ * H_, 2);   // 1600 groups x 2 query blocks of 150
    attn_kernel<<<g2, NTHR, ATTN_SMEM>>>(bias_table);

    merge_gemm<<<(NTOK + 63) / 64, 256>>>(w_merge, b_merge, out);
}